// round 6
// baseline (speedup 1.0000x reference)
#include <cuda_runtime.h>
#include <cstdint>

#define MAX_N 100000
#define MAX_E 1600000
#define D 128
#define D4 (D/4)

// ---------------------------------------------------------------------------
// Static scratch (__device__ globals per alloc rules)
// ---------------------------------------------------------------------------
__device__ float g_y[(size_t)MAX_N * D];       // y = x @ W
__device__ int   g_deg[MAX_N];
__device__ int   g_pos[MAX_N];
__device__ int   g_off[MAX_N + 1];
__device__ int   g_part[256];
__device__ int   g_srcs[MAX_E];

// ---------------------------------------------------------------------------
// tf32 helpers
// ---------------------------------------------------------------------------
__device__ __forceinline__ unsigned f2tf32(float f) {
    unsigned u;
    asm("cvt.rna.tf32.f32 %0, %1;" : "=r"(u) : "f"(f));
    return u;
}

__device__ __forceinline__ void mma_tf32(float* d, const unsigned* a,
                                         unsigned b0, unsigned b1) {
    asm volatile(
        "mma.sync.aligned.m16n8k8.row.col.f32.tf32.tf32.f32 "
        "{%0,%1,%2,%3}, {%4,%5,%6,%7}, {%8,%9}, {%0,%1,%2,%3};"
        : "+f"(d[0]), "+f"(d[1]), "+f"(d[2]), "+f"(d[3])
        : "r"(a[0]), "r"(a[1]), "r"(a[2]), "r"(a[3]), "r"(b0), "r"(b1));
}

// ---------------------------------------------------------------------------
// GEMM (tf32 tensor cores): y = x @ W      (N x 128) @ (128 x 128)
// Block: 128 rows, 256 threads (8 warps in 4x2 grid), warp tile 32x64.
// ---------------------------------------------------------------------------
#define GEMM_THREADS 256
#define TILE_M 128
#define LDR 132                    // smem row stride in floats (128 + 4 pad)

__global__ void gemm_tf32_kernel(const float4* __restrict__ x4,
                                 const float4* __restrict__ W4,
                                 float* __restrict__ y, int N) {
    extern __shared__ float smf[];
    float* As = smf;                       // [128][132]
    float* Bs = smf + TILE_M * LDR;        // [128][132]
    float4* As4 = reinterpret_cast<float4*>(As);   // row stride 33
    float4* Bs4 = reinterpret_cast<float4*>(Bs);

    const int tid = threadIdx.x;
    const int row0 = blockIdx.x * TILE_M;
    const float4 z4 = make_float4(0.f, 0.f, 0.f, 0.f);

    // Stage x-tile and W into smem, converting to tf32 bit patterns.
#pragma unroll
    for (int i = 0; i < 16; i++) {
        int idx = i * GEMM_THREADS + tid;   // 0..4095
        int r = idx >> 5;                   // 0..127
        int c = idx & 31;                   // 0..31
        float4 av = (row0 + r < N) ? x4[(size_t)(row0 + r) * D4 + c] : z4;
        float4 wv = W4[r * D4 + c];
        av.x = __uint_as_float(f2tf32(av.x));
        av.y = __uint_as_float(f2tf32(av.y));
        av.z = __uint_as_float(f2tf32(av.z));
        av.w = __uint_as_float(f2tf32(av.w));
        wv.x = __uint_as_float(f2tf32(wv.x));
        wv.y = __uint_as_float(f2tf32(wv.y));
        wv.z = __uint_as_float(f2tf32(wv.z));
        wv.w = __uint_as_float(f2tf32(wv.w));
        As4[r * 33 + c] = av;
        Bs4[r * 33 + c] = wv;
    }
    __syncthreads();

    const int warp = tid >> 5;
    const int lane = tid & 31;
    const int wr = warp >> 1;      // 0..3 : rows wr*32 .. +32
    const int wc = warp & 1;       // 0..1 : cols wc*64 .. +64
    const int lr = lane >> 2;      // 0..7
    const int lc = lane & 3;       // 0..3

    float d[2][8][4];
#pragma unroll
    for (int mt = 0; mt < 2; mt++)
#pragma unroll
        for (int nt = 0; nt < 8; nt++)
#pragma unroll
            for (int q = 0; q < 4; q++) d[mt][nt][q] = 0.f;

#pragma unroll
    for (int ks = 0; ks < 16; ks++) {
        const int k0 = ks * 8;
        unsigned a[2][4];
#pragma unroll
        for (int mt = 0; mt < 2; mt++) {
            int rb = wr * 32 + mt * 16;
            a[mt][0] = __float_as_uint(As[(rb + lr)     * LDR + k0 + lc]);
            a[mt][1] = __float_as_uint(As[(rb + lr + 8) * LDR + k0 + lc]);
            a[mt][2] = __float_as_uint(As[(rb + lr)     * LDR + k0 + lc + 4]);
            a[mt][3] = __float_as_uint(As[(rb + lr + 8) * LDR + k0 + lc + 4]);
        }
#pragma unroll
        for (int nt = 0; nt < 8; nt++) {
            int cn = wc * 64 + nt * 8;
            unsigned b0 = __float_as_uint(Bs[(k0 + lc)     * LDR + cn + lr]);
            unsigned b1 = __float_as_uint(Bs[(k0 + lc + 4) * LDR + cn + lr]);
            mma_tf32(d[0][nt], a[0], b0, b1);
            mma_tf32(d[1][nt], a[1], b0, b1);
        }
    }

    // Epilogue: write y (no bias here; bias lands in the aggregate pass).
#pragma unroll
    for (int mt = 0; mt < 2; mt++) {
        int rbase = row0 + wr * 32 + mt * 16 + lr;
#pragma unroll
        for (int nt = 0; nt < 8; nt++) {
            int cn = wc * 64 + nt * 8 + 2 * lc;
            if (rbase < N)
                *reinterpret_cast<float2*>(y + (size_t)rbase * D + cn) =
                    make_float2(d[mt][nt][0], d[mt][nt][1]);
            if (rbase + 8 < N)
                *reinterpret_cast<float2*>(y + (size_t)(rbase + 8) * D + cn) =
                    make_float2(d[mt][nt][2], d[mt][nt][3]);
        }
    }
}

// ---------------------------------------------------------------------------
// CSR build: histogram -> scan -> fill
// ---------------------------------------------------------------------------
__global__ void hist_kernel(const int* __restrict__ ei, int* __restrict__ deg, int E) {
    int i = blockIdx.x * blockDim.x + threadIdx.x;
    if (i < E) atomicAdd(&deg[ei[E + i]], 1);
}

#define SCAN_T 256
#define SCAN_ELEMS 1024

__global__ void scanA_kernel(const int* __restrict__ deg, int* __restrict__ part, int N) {
    __shared__ int s[SCAN_T];
    int base = blockIdx.x * SCAN_ELEMS + threadIdx.x * 4;
    int sum = 0;
#pragma unroll
    for (int i = 0; i < 4; i++) {
        int idx = base + i;
        if (idx < N) sum += deg[idx];
    }
    s[threadIdx.x] = sum;
    __syncthreads();
    for (int stride = SCAN_T / 2; stride > 0; stride >>= 1) {
        if (threadIdx.x < stride) s[threadIdx.x] += s[threadIdx.x + stride];
        __syncthreads();
    }
    if (threadIdx.x == 0) part[blockIdx.x] = s[0];
}

__global__ void scanB_kernel(int* __restrict__ part, int* __restrict__ off,
                             int nblocks, int N) {
    if (threadIdx.x == 0 && blockIdx.x == 0) {
        int run = 0;
        for (int i = 0; i < nblocks; i++) {
            int v = part[i];
            part[i] = run;
            run += v;
        }
        off[N] = run;
    }
}

__global__ void scanC_kernel(const int* __restrict__ deg, const int* __restrict__ part,
                             int* __restrict__ off, int N) {
    __shared__ int s[SCAN_T];
    int base = blockIdx.x * SCAN_ELEMS + threadIdx.x * 4;
    int v[4];
    int sum = 0;
#pragma unroll
    for (int i = 0; i < 4; i++) {
        int idx = base + i;
        v[i] = (idx < N) ? deg[idx] : 0;
        sum += v[i];
    }
    s[threadIdx.x] = sum;
    __syncthreads();
    for (int stride = 1; stride < SCAN_T; stride <<= 1) {
        int add = (threadIdx.x >= stride) ? s[threadIdx.x - stride] : 0;
        __syncthreads();
        s[threadIdx.x] += add;
        __syncthreads();
    }
    int excl = part[blockIdx.x] + s[threadIdx.x] - sum;
#pragma unroll
    for (int i = 0; i < 4; i++) {
        int idx = base + i;
        if (idx < N) off[idx] = excl;
        excl += v[i];
    }
}

__global__ void fill_kernel(const int* __restrict__ ei, const int* __restrict__ off,
                            int* __restrict__ pos, int* __restrict__ srcs, int E) {
    int i = blockIdx.x * blockDim.x + threadIdx.x;
    if (i < E) {
        int dst = ei[E + i];
        int p = atomicAdd(&pos[dst], 1);
        srcs[off[dst] + p] = ei[i];
    }
}

// ---------------------------------------------------------------------------
// Aggregate + bias: out[n,:] = sum_{src in bucket n} y[src,:] + b[:]
// Warp per node.
// ---------------------------------------------------------------------------
__global__ void agg_bias_kernel(const float4* __restrict__ y4,
                                const int* __restrict__ off,
                                const int* __restrict__ srcs,
                                const float4* __restrict__ b4,
                                float4* __restrict__ out4, int N) {
    int node = (blockIdx.x * blockDim.x + threadIdx.x) >> 5;
    if (node >= N) return;
    int lane = threadIdx.x & 31;

    int j = off[node];
    int jend = off[node + 1];

    float4 acc = make_float4(0.f, 0.f, 0.f, 0.f);
    for (; j + 4 <= jend; j += 4) {
        int s0 = __ldg(&srcs[j]);
        int s1 = __ldg(&srcs[j + 1]);
        int s2 = __ldg(&srcs[j + 2]);
        int s3 = __ldg(&srcs[j + 3]);
        float4 v0 = __ldg(&y4[(size_t)s0 * D4 + lane]);
        float4 v1 = __ldg(&y4[(size_t)s1 * D4 + lane]);
        float4 v2 = __ldg(&y4[(size_t)s2 * D4 + lane]);
        float4 v3 = __ldg(&y4[(size_t)s3 * D4 + lane]);
        acc.x += (v0.x + v1.x) + (v2.x + v3.x);
        acc.y += (v0.y + v1.y) + (v2.y + v3.y);
        acc.z += (v0.z + v1.z) + (v2.z + v3.z);
        acc.w += (v0.w + v1.w) + (v2.w + v3.w);
    }
    for (; j < jend; j++) {
        int s0 = __ldg(&srcs[j]);
        float4 v0 = __ldg(&y4[(size_t)s0 * D4 + lane]);
        acc.x += v0.x; acc.y += v0.y; acc.z += v0.z; acc.w += v0.w;
    }
    float4 bb = b4[lane];
    acc.x += bb.x; acc.y += bb.y; acc.z += bb.z; acc.w += bb.w;
    out4[(size_t)node * D4 + lane] = acc;
}

// ---------------------------------------------------------------------------
// Launch
// ---------------------------------------------------------------------------
extern "C" void kernel_launch(void* const* d_in, const int* in_sizes, int n_in,
                              void* d_out, int out_size) {
    const float* x = (const float*)d_in[0];
    const int* ei = (const int*)d_in[1];
    const float* W = (const float*)d_in[2];
    const float* b = (const float*)d_in[3];
    float* out = (float*)d_out;

    const int N = in_sizes[0] / D;
    const int E = in_sizes[1] / 2;

    float* y;  int* deg;  int* pos;  int* off;  int* part;  int* srcs;
    cudaGetSymbolAddress((void**)&y,    g_y);
    cudaGetSymbolAddress((void**)&deg,  g_deg);
    cudaGetSymbolAddress((void**)&pos,  g_pos);
    cudaGetSymbolAddress((void**)&off,  g_off);
    cudaGetSymbolAddress((void**)&part, g_part);
    cudaGetSymbolAddress((void**)&srcs, g_srcs);

    cudaMemsetAsync(deg, 0, N * sizeof(int));
    cudaMemsetAsync(pos, 0, N * sizeof(int));

    // GEMM first (edge-independent): y = x @ W  on tensor cores
    {
        int smem = 2 * TILE_M * LDR * (int)sizeof(float);   // 135168 B
        cudaFuncSetAttribute(gemm_tf32_kernel,
                             cudaFuncAttributeMaxDynamicSharedMemorySize, smem);
        int blocks = (N + TILE_M - 1) / TILE_M;
        gemm_tf32_kernel<<<blocks, GEMM_THREADS, smem>>>(
            (const float4*)x, (const float4*)W, y, N);
    }

    // CSR build
    {
        int threads = 256;
        hist_kernel<<<(E + threads - 1) / threads, threads>>>(ei, deg, E);
    }
    int nblocks = (N + SCAN_ELEMS - 1) / SCAN_ELEMS;
    scanA_kernel<<<nblocks, SCAN_T>>>(deg, part, N);
    scanB_kernel<<<1, 32>>>(part, off, nblocks, N);
    scanC_kernel<<<nblocks, SCAN_T>>>(deg, part, off, N);
    {
        int threads = 256;
        fill_kernel<<<(E + threads - 1) / threads, threads>>>(ei, off, pos, srcs, E);
    }

    // Aggregate y into out with bias
    {
        int threads = 256;
        int blocks = (N + 7) / 8;
        agg_bias_kernel<<<blocks, threads>>>(
            (const float4*)y, off, srcs, (const float4*)b, (float4*)out, N);
    }
}